// round 11
// baseline (speedup 1.0000x reference)
#include <cuda_runtime.h>
#include <stdint.h>

#define V_SIZE 50000
#define D_DIM  300
#define ROWW   160      // uint32 words per row: 10 chunks * 4 quads * 4 words (640B)
#define NCH    10       // k32 chunks covering 320 padded dims
#define Q_LEN  16
#define T_LEN  1024
#define NTHR   256

// Quantized normalized embeddings, fragment-ordered for mma.m16n8k32.s8:
// per row: 10 chunks x 4 quads x uint4{hi_k[4j..4j+3], hi_k[16+4j..], lo_k[4j..], lo_k[16+4j..]}
// hi = round(256*x), lo = round(65536*(x - hi/256)); row 0 (PAD) all zero.
__device__ uint32_t g_q[(size_t)V_SIZE * ROWW];

// ---------------- prep: normalize + int8 hi/lo quantize + fragment order ----------------
__global__ void prep_kernel(const float* __restrict__ emb) {
    __shared__ float xs[8][320];
    int row = blockIdx.x * 8 + threadIdx.y;
    if (row >= V_SIZE) return;
    int lane = threadIdx.x;
    int wy = threadIdx.y;
    const float* r = emb + (size_t)row * D_DIM;
    float s = 0.f;
    #pragma unroll
    for (int i = 0; i < 10; i++) {
        int d = lane + 32 * i;
        float v = (d < D_DIM) ? r[d] : 0.f;
        xs[wy][d] = v;
        s += v * v;
    }
    #pragma unroll
    for (int o = 16; o > 0; o >>= 1) s += __shfl_xor_sync(0xffffffffu, s, o);
    s = __shfl_sync(0xffffffffu, s, 0);
    float rn = (row == 0) ? 0.f : 1.f / (sqrtf(s) + 1e-9f);
    __syncwarp();

    uint32_t* dst = g_q + (size_t)row * ROWW;
    #pragma unroll
    for (int k = 0; k < 5; k++) {
        int W = lane + 32 * k;
        int U = W >> 2, comp = W & 3;
        int c = U >> 2, j = U & 3;
        int plane = comp >> 1, h = comp & 1;
        uint32_t word = 0;
        #pragma unroll
        for (int b = 0; b < 4; b++) {
            int d = 32 * c + 16 * h + 4 * j + b;
            float x = xs[wy][d] * rn;
            float hif = rintf(x * 256.f);
            int byte_v;
            if (plane == 0) {
                int hv = (int)hif;
                byte_v = hv < -127 ? -127 : (hv > 127 ? 127 : hv);
            } else {
                float res = x - hif * (1.f / 256.f);
                int lo = (int)rintf(res * 65536.f);
                byte_v = lo < -127 ? -127 : (lo > 127 ? 127 : lo);
            }
            word |= (uint32_t)(uint8_t)(int8_t)byte_v << (8 * b);
        }
        dst[W] = word;
    }
}

// mma.sync m16n8k32 row.col s32.s8.s8.s32  (base sm_80+ feature, OK on sm_103)
#define IMMA(c, a0, a1, a2, a3, b0, b1)                                       \
    asm volatile("mma.sync.aligned.m16n8k32.row.col.s32.s8.s8.s32 "           \
        "{%0,%1,%2,%3}, {%4,%5,%6,%7}, {%8,%9}, {%0,%1,%2,%3};"               \
        : "+r"((c)[0]), "+r"((c)[1]), "+r"((c)[2]), "+r"((c)[3])              \
        : "r"(a0), "r"(a1), "r"(a2), "r"(a3), "r"(b0), "r"(b1))

#define K1SC 1.52587890625e-05f   // 2^-16
#define K2SC 5.9604644775390625e-08f  // 2^-24

// ---------------- main kernel: one CTA per (batch, doc) ----------------
__global__ __launch_bounds__(NTHR, 2) void knrm_mma_kernel(
    const int*   __restrict__ posdoc,
    const int*   __restrict__ negdoc,
    const int*   __restrict__ query,
    const float* __restrict__ W,
    const float* __restrict__ bparam,
    float*       __restrict__ out)
{
    // B tiles: [chunk][n][quad] uint4, addr_units = c*64 + n*4 + j  (conflict-free LDS.128)
    __shared__ uint4 Bsm[NCH * 64];          // 10 KB
    __shared__ float wacc[8 * 192];
    __shared__ float red[192];
    __shared__ int   qtok[Q_LEN];
    __shared__ float spart[11];

    const int tid  = threadIdx.x;
    const int w    = tid >> 5;
    const int lane = tid & 31;
    const int bi    = blockIdx.x >> 1;
    const int which = blockIdx.x & 1;
    const int* doc  = which ? negdoc : posdoc;

    if (tid < Q_LEN) qtok[tid] = query[bi * Q_LEN + tid];
    __syncthreads();

    // ---- build B tiles (query): pure uint4 copy (A frag grouping == B frag grouping) ----
    for (int idx = tid; idx < NCH * 64; idx += NTHR) {
        int c = idx >> 6;
        int rem = idx & 63;
        int n = rem >> 2, j = rem & 3;
        const uint4* src = (const uint4*)(g_q + (size_t)qtok[n] * ROWW);
        Bsm[c * 64 + n * 4 + j] = src[c * 4 + j];
    }
    __syncthreads();

    const int j4   = lane & 3;
    const int bu0  = (lane >> 2) * 4 + j4;        // n-half 0 slot
    const int bu1  = bu0 + 32;                    // n-half 1 slot

    float kacc[44];
    float ssum4[4];
    #pragma unroll
    for (int v = 0; v < 44; v++) kacc[v] = 0.f;
    #pragma unroll
    for (int v = 0; v < 4; v++) ssum4[v] = 0.f;

    const float cB[10] = {-90.f,-70.f,-50.f,-30.f,-10.f,10.f,30.f,50.f,70.f,90.f};
    const float cC[10] = {2.5767571e-18f, 2.2897348e-11f, 3.7266532e-06f,
                          1.1108997e-02f, 6.0653067e-01f, 6.0653067e-01f,
                          1.1108997e-02f, 3.7266532e-06f, 2.2897348e-11f,
                          2.5767571e-18f};

    const int dbase = bi * T_LEN + w * 128;

    for (int tt = 0; tt < 8; tt++) {
        const int tokA = doc[dbase + tt * 16 + (lane >> 2)];       // rows 0-7
        const int tokB = doc[dbase + tt * 16 + 8 + (lane >> 2)];   // rows 8-15
        const uint4* pa = (const uint4*)(g_q + (size_t)tokA * ROWW) + j4;
        const uint4* pb = (const uint4*)(g_q + (size_t)tokB * ROWW) + j4;

        int acc1a[4] = {0,0,0,0};   // hh, n 0-7
        int acc1b[4] = {0,0,0,0};   // hh, n 8-15
        int acc2a[4] = {0,0,0,0};   // lh+hl, n 0-7
        int acc2b[4] = {0,0,0,0};   // lh+hl, n 8-15

        uint4 va = pa[0];
        uint4 vb = pb[0];

        #pragma unroll
        for (int c = 0; c < NCH; c++) {
            uint4 na = va, nb = vb;
            if (c < NCH - 1) {
                na = pa[(c + 1) * 4];
                nb = pb[(c + 1) * 4];
            }
            uint4 B0 = Bsm[c * 64 + bu0];
            uint4 B1 = Bsm[c * 64 + bu1];

            IMMA(acc1a, va.x, vb.x, va.y, vb.y, B0.x, B0.y);   // hi*hi
            IMMA(acc1b, va.x, vb.x, va.y, vb.y, B1.x, B1.y);
            IMMA(acc2a, va.z, vb.z, va.w, vb.w, B0.x, B0.y);   // lo*hi
            IMMA(acc2b, va.z, vb.z, va.w, vb.w, B1.x, B1.y);
            IMMA(acc2a, va.x, vb.x, va.y, vb.y, B0.z, B0.w);   // hi*lo
            IMMA(acc2b, va.x, vb.x, va.y, vb.y, B1.z, B1.w);

            va = na; vb = nb;
        }

        // ---- fused RBF epilogue on C-fragment registers ----
        #pragma unroll
        for (int nh = 0; nh < 2; nh++) {
            #pragma unroll
            for (int j = 0; j < 4; j++) {
                int a1 = nh ? acc1b[j] : acc1a[j];
                int a2 = nh ? acc2b[j] : acc2a[j];
                float s = fmaf((float)a2, K2SC, (float)a1 * K1SC);
                int c2 = nh * 2 + (j & 1);
                ssum4[c2] += s;
                float A = -50.f * s * s;
                #pragma unroll
                for (int k = 0; k < 10; k++)
                    kacc[k * 4 + c2] += cC[k] * __expf(fmaf(cB[k], s, A));
                float d1 = s - 1.f;
                kacc[40 + c2] += __expf(-500000.f * d1 * d1);
            }
        }
    }

    // ---- warp reduce over row-group lanes (bits 2..4 of lane) ----
    #pragma unroll
    for (int v = 0; v < 44; v++) {
        float x = kacc[v];
        x += __shfl_xor_sync(0xffffffffu, x, 4);
        x += __shfl_xor_sync(0xffffffffu, x, 8);
        x += __shfl_xor_sync(0xffffffffu, x, 16);
        kacc[v] = x;
    }
    #pragma unroll
    for (int c2 = 0; c2 < 4; c2++) {
        float x = ssum4[c2];
        x += __shfl_xor_sync(0xffffffffu, x, 4);
        x += __shfl_xor_sync(0xffffffffu, x, 8);
        x += __shfl_xor_sync(0xffffffffu, x, 16);
        ssum4[c2] = x;
    }

    if (lane < 4) {
        #pragma unroll
        for (int k = 0; k < 11; k++) {
            wacc[w * 192 + k * 16 + 2 * lane    ] = kacc[k * 4 + 0];
            wacc[w * 192 + k * 16 + 2 * lane + 1] = kacc[k * 4 + 1];
            wacc[w * 192 + k * 16 + 2 * lane + 8] = kacc[k * 4 + 2];
            wacc[w * 192 + k * 16 + 2 * lane + 9] = kacc[k * 4 + 3];
        }
        wacc[w * 192 + 176 + 2 * lane    ] = ssum4[0];
        wacc[w * 192 + 176 + 2 * lane + 1] = ssum4[1];
        wacc[w * 192 + 176 + 2 * lane + 8] = ssum4[2];
        wacc[w * 192 + 176 + 2 * lane + 9] = ssum4[3];
    }
    __syncthreads();

    if (tid < 192) {
        float s = 0.f;
        #pragma unroll
        for (int ww = 0; ww < 8; ww++) s += wacc[ww * 192 + tid];
        red[tid] = s;
    }
    __syncthreads();

    if (tid < 11) {
        float qk = 0.f;
        #pragma unroll
        for (int q = 0; q < Q_LEN; q++)
            if (red[176 + q] != 0.0f) qk += logf(red[tid * 16 + q] + 1e-6f);
        spart[tid] = qk * W[tid];
    }
    __syncthreads();
    if (tid == 0) {
        float s = bparam[0];
        #pragma unroll
        for (int k = 0; k < 11; k++) s += spart[k];
        out[bi * 2 + which] = s;
    }
}

extern "C" void kernel_launch(void* const* d_in, const int* in_sizes, int n_in,
                              void* d_out, int out_size) {
    const int*   posdoc = (const int*)d_in[0];
    const int*   negdoc = (const int*)d_in[1];
    const int*   query  = (const int*)d_in[2];
    // d_in[3] = query_idf (unused)
    const float* emb    = (const float*)d_in[4];
    // d_in[5] = mus, d_in[6] = sigmas (compile-time folded)
    const float* W      = (const float*)d_in[7];
    const float* bparam = (const float*)d_in[8];
    float* out = (float*)d_out;

    prep_kernel<<<(V_SIZE + 7) / 8, dim3(32, 8)>>>(emb);
    knrm_mma_kernel<<<512, NTHR>>>(posdoc, negdoc, query, W, bparam, out);
}

// round 12
// speedup vs baseline: 2.4969x; 2.4969x over previous
#include <cuda_runtime.h>
#include <cuda_fp16.h>
#include <stdint.h>

#define V_SIZE 50000
#define D_DIM  300
#define ROWW   160      // uint32 words per row (320 fp16 = 640B)
#define NCH    20       // k16 chunks over 320 padded dims
#define Q_LEN  16
#define T_LEN  1024
#define NTHR   256

// fp16 normalized embeddings, fragment-ordered for mma.m16n8k16:
// word W = (c>>1)*16 + j*4 + (c&1)*2 + wslot  holds fp16x2 of elements
// d0 = c*16 + wslot*8 + 2j, d0+1.  Row 0 (PAD) zeroed.
__device__ uint32_t g_h[(size_t)V_SIZE * ROWW];

// ---------------- prep: normalize + fp16 + fragment order ----------------
__global__ void prep_kernel(const float* __restrict__ emb) {
    __shared__ float xs[8][320];
    int row = blockIdx.x * 8 + threadIdx.y;
    if (row >= V_SIZE) return;
    int lane = threadIdx.x;
    int wy = threadIdx.y;
    const float4* r4 = (const float4*)(emb + (size_t)row * D_DIM);  // 75 float4
    float s = 0.f;
    #pragma unroll
    for (int i = 0; i < 3; i++) {
        int idx = lane + 32 * i;
        if (idx < 75) {
            float4 v = r4[idx];
            xs[wy][idx * 4 + 0] = v.x;
            xs[wy][idx * 4 + 1] = v.y;
            xs[wy][idx * 4 + 2] = v.z;
            xs[wy][idx * 4 + 3] = v.w;
            s += v.x * v.x + v.y * v.y + v.z * v.z + v.w * v.w;
        }
    }
    if (lane < 20) xs[wy][300 + lane] = 0.f;
    #pragma unroll
    for (int o = 16; o > 0; o >>= 1) s += __shfl_xor_sync(0xffffffffu, s, o);
    s = __shfl_sync(0xffffffffu, s, 0);
    float rn = (row == 0) ? 0.f : 1.f / (sqrtf(s) + 1e-9f);
    __syncwarp();

    uint32_t* dst = g_h + (size_t)row * ROWW;
    #pragma unroll
    for (int k = 0; k < 5; k++) {
        int W = lane + 32 * k;
        int pair  = W >> 4;
        int rem   = W & 15;
        int j     = rem >> 2;
        int cl    = (rem >> 1) & 1;
        int wslot = rem & 1;
        int c  = pair * 2 + cl;
        int d0 = c * 16 + wslot * 8 + 2 * j;
        __half2 h2 = __floats2half2_rn(xs[wy][d0] * rn, xs[wy][d0 + 1] * rn);
        dst[W] = *(uint32_t*)&h2;
    }
}

// mma.sync m16n8k16 row.col f32.f16.f16.f32
#define MMA(c, a0, a1, a2, a3, b0, b1)                                        \
    asm volatile("mma.sync.aligned.m16n8k16.row.col.f32.f16.f16.f32 "         \
        "{%0,%1,%2,%3}, {%4,%5,%6,%7}, {%8,%9}, {%0,%1,%2,%3};"               \
        : "+f"((c)[0]), "+f"((c)[1]), "+f"((c)[2]), "+f"((c)[3])              \
        : "r"(a0), "r"(a1), "r"(a2), "r"(a3), "r"(b0), "r"(b1))

// ---------------- main kernel: one CTA per (batch, doc) ----------------
__global__ __launch_bounds__(NTHR, 2) void knrm_mma_kernel(
    const int*   __restrict__ posdoc,
    const int*   __restrict__ negdoc,
    const int*   __restrict__ query,
    const float* __restrict__ W,
    const float* __restrict__ bparam,
    float*       __restrict__ out)
{
    // B tiles: [c][h][n][j] uint2; LDS addr linear in lane -> conflict-free
    __shared__ uint2 Bsm[NCH * 2 * 32];      // 10 KB
    __shared__ float wacc[8 * 192];
    __shared__ float red[192];
    __shared__ int   qtok[Q_LEN];
    __shared__ float spart[11];

    const int tid  = threadIdx.x;
    const int w    = tid >> 5;
    const int lane = tid & 31;
    const int bi    = blockIdx.x >> 1;
    const int which = blockIdx.x & 1;
    const int* doc  = which ? negdoc : posdoc;

    if (tid < Q_LEN) qtok[tid] = query[bi * Q_LEN + tid];
    __syncthreads();

    // ---- build B tiles (query): uint2 copies from fragment-ordered rows ----
    for (int idx = tid; idx < NCH * 2 * 32; idx += NTHR) {
        int j = idx & 3;
        int n = (idx >> 2) & 7;
        int h = (idx >> 5) & 1;
        int c = idx >> 6;
        const uint32_t* src = g_h + (size_t)qtok[h * 8 + n] * ROWW +
                              (c >> 1) * 16 + j * 4 + (c & 1) * 2;
        Bsm[idx] = make_uint2(src[0], src[1]);
    }
    __syncthreads();

    const int j4 = lane & 3;

    float kacc[44];
    float ssum4[4];
    #pragma unroll
    for (int v = 0; v < 44; v++) kacc[v] = 0.f;
    #pragma unroll
    for (int v = 0; v < 4; v++) ssum4[v] = 0.f;

    const float cC[10] = {2.5767571e-18f, 2.2897348e-11f, 3.7266532e-06f,
                          1.1108997e-02f, 6.0653067e-01f, 6.0653067e-01f,
                          1.1108997e-02f, 3.7266532e-06f, 2.2897348e-11f,
                          2.5767571e-18f};

    const int dbase = bi * T_LEN + w * 128;

    for (int tt = 0; tt < 8; tt++) {
        const int tokA = doc[dbase + tt * 16 + (lane >> 2)];       // rows 0-7
        const int tokB = doc[dbase + tt * 16 + 8 + (lane >> 2)];   // rows 8-15
        const uint4* pa = (const uint4*)(g_h + (size_t)tokA * ROWW) + j4;
        const uint4* pb = (const uint4*)(g_h + (size_t)tokB * ROWW) + j4;

        float c0[4] = {0.f, 0.f, 0.f, 0.f};   // q cols 0-7
        float c1[4] = {0.f, 0.f, 0.f, 0.f};   // q cols 8-15

        uint4 va = pa[0];   // chunks 2p, 2p+1: (a0,a2) even, (a0,a2) odd
        uint4 vb = pb[0];   // rows +8: (a1,a3) pairs

        #pragma unroll
        for (int p = 0; p < 10; p++) {
            uint4 na = va, nb = vb;
            if (p < 9) {
                na = pa[(p + 1) * 4];
                nb = pb[(p + 1) * 4];
            }
            // chunk 2p
            {
                const int c = 2 * p;
                uint2 B0 = Bsm[(c * 2 + 0) * 32 + lane];
                uint2 B1 = Bsm[(c * 2 + 1) * 32 + lane];
                MMA(c0, va.x, vb.x, va.y, vb.y, B0.x, B0.y);
                MMA(c1, va.x, vb.x, va.y, vb.y, B1.x, B1.y);
            }
            // chunk 2p+1
            {
                const int c = 2 * p + 1;
                uint2 B0 = Bsm[(c * 2 + 0) * 32 + lane];
                uint2 B1 = Bsm[(c * 2 + 1) * 32 + lane];
                MMA(c0, va.z, vb.z, va.w, vb.w, B0.x, B0.y);
                MMA(c1, va.z, vb.z, va.w, vb.w, B1.x, B1.y);
            }
            va = na; vb = nb;
        }

        // ---- fused RBF epilogue on C-fragment registers ----
        #pragma unroll
        for (int nh = 0; nh < 2; nh++) {
            #pragma unroll
            for (int j = 0; j < 4; j++) {
                float s = nh ? c1[j] : c0[j];
                int c2 = nh * 2 + (j & 1);
                ssum4[c2] += s;
                float A = -50.f * s * s;
                float e = __expf(A);
                float u = __expf(10.f * s);
                float r;
                asm("rcp.approx.f32 %0, %1;" : "=f"(r) : "f"(u));
                float u2 = u * u, u3 = u2 * u, u5 = u3 * u2, u7 = u5 * u2;
                float r2 = r * r, r3 = r2 * r, r5 = r3 * r2, r7 = r5 * r2;
                kacc[0 * 4 + c2] += cC[0] * __expf(fmaf(-90.f, s, A));
                kacc[1 * 4 + c2] += cC[1] * (e * r7);
                kacc[2 * 4 + c2] += cC[2] * (e * r5);
                kacc[3 * 4 + c2] += cC[3] * (e * r3);
                kacc[4 * 4 + c2] += cC[4] * (e * r);
                kacc[5 * 4 + c2] += cC[5] * (e * u);
                kacc[6 * 4 + c2] += cC[6] * (e * u3);
                kacc[7 * 4 + c2] += cC[7] * (e * u5);
                kacc[8 * 4 + c2] += cC[8] * (e * u7);
                kacc[9 * 4 + c2] += cC[9] * __expf(fmaf(90.f, s, A));
                float d1 = s - 1.f;
                kacc[40 + c2] += __expf(-500000.f * d1 * d1);
            }
        }
    }

    // ---- warp reduce over row-group lanes (bits 2..4 of lane) ----
    #pragma unroll
    for (int v = 0; v < 44; v++) {
        float x = kacc[v];
        x += __shfl_xor_sync(0xffffffffu, x, 4);
        x += __shfl_xor_sync(0xffffffffu, x, 8);
        x += __shfl_xor_sync(0xffffffffu, x, 16);
        kacc[v] = x;
    }
    #pragma unroll
    for (int c2 = 0; c2 < 4; c2++) {
        float x = ssum4[c2];
        x += __shfl_xor_sync(0xffffffffu, x, 4);
        x += __shfl_xor_sync(0xffffffffu, x, 8);
        x += __shfl_xor_sync(0xffffffffu, x, 16);
        ssum4[c2] = x;
    }

    if (lane < 4) {
        #pragma unroll
        for (int k = 0; k < 11; k++) {
            wacc[w * 192 + k * 16 + 2 * lane    ] = kacc[k * 4 + 0];
            wacc[w * 192 + k * 16 + 2 * lane + 1] = kacc[k * 4 + 1];
            wacc[w * 192 + k * 16 + 2 * lane + 8] = kacc[k * 4 + 2];
            wacc[w * 192 + k * 16 + 2 * lane + 9] = kacc[k * 4 + 3];
        }
        wacc[w * 192 + 176 + 2 * lane    ] = ssum4[0];
        wacc[w * 192 + 176 + 2 * lane + 1] = ssum4[1];
        wacc[w * 192 + 176 + 2 * lane + 8] = ssum4[2];
        wacc[w * 192 + 176 + 2 * lane + 9] = ssum4[3];
    }
    __syncthreads();

    if (tid < 192) {
        float s = 0.f;
        #pragma unroll
        for (int ww = 0; ww < 8; ww++) s += wacc[ww * 192 + tid];
        red[tid] = s;
    }
    __syncthreads();

    if (tid < 11) {
        float qk = 0.f;
        #pragma unroll
        for (int q = 0; q < Q_LEN; q++)
            if (red[176 + q] != 0.0f) qk += logf(red[tid * 16 + q] + 1e-6f);
        spart[tid] = qk * W[tid];
    }
    __syncthreads();
    if (tid == 0) {
        float s = bparam[0];
        #pragma unroll
        for (int k = 0; k < 11; k++) s += spart[k];
        out[bi * 2 + which] = s;
    }
}

extern "C" void kernel_launch(void* const* d_in, const int* in_sizes, int n_in,
                              void* d_out, int out_size) {
    const int*   posdoc = (const int*)d_in[0];
    const int*   negdoc = (const int*)d_in[1];
    const int*   query  = (const int*)d_in[2];
    // d_in[3] = query_idf (unused)
    const float* emb    = (const float*)d_in[4];
    // d_in[5] = mus, d_in[6] = sigmas (compile-time folded)
    const float* W      = (const float*)d_in[7];
    const float* bparam = (const float*)d_in[8];
    float* out = (float*)d_out;

    prep_kernel<<<(V_SIZE + 7) / 8, dim3(32, 8)>>>(emb);
    knrm_mma_kernel<<<512, NTHR>>>(posdoc, negdoc, query, W, bparam, out);
}

// round 13
// speedup vs baseline: 2.7320x; 1.0941x over previous
#include <cuda_runtime.h>
#include <cuda_fp16.h>
#include <stdint.h>

#define V_SIZE 50000
#define D_DIM  300
#define ROWW   160      // uint32 words per row (320 fp16 = 640B)
#define NCH    20       // k16 chunks over 320 padded dims
#define Q_LEN  16
#define T_LEN  1024
#define NTHR   128
#define NWARP  4
#define TPW    16       // tiles per warp (16 tokens each)

// fp16 normalized embeddings, fragment-ordered for mma.m16n8k16:
// word W = (c>>1)*16 + j*4 + (c&1)*2 + wslot  holds fp16x2 of elements
// d0 = c*16 + wslot*8 + 2j, d0+1.  Row 0 (PAD) zeroed.
__device__ uint32_t g_h[(size_t)V_SIZE * ROWW];

// ---------------- prep: normalize + fp16 + fragment order ----------------
__global__ void prep_kernel(const float* __restrict__ emb) {
    __shared__ float xs[8][320];
    int row = blockIdx.x * 8 + threadIdx.y;
    if (row >= V_SIZE) return;
    int lane = threadIdx.x;
    int wy = threadIdx.y;
    const float4* r4 = (const float4*)(emb + (size_t)row * D_DIM);  // 75 float4
    float s = 0.f;
    #pragma unroll
    for (int i = 0; i < 3; i++) {
        int idx = lane + 32 * i;
        if (idx < 75) {
            float4 v = r4[idx];
            xs[wy][idx * 4 + 0] = v.x;
            xs[wy][idx * 4 + 1] = v.y;
            xs[wy][idx * 4 + 2] = v.z;
            xs[wy][idx * 4 + 3] = v.w;
            s += v.x * v.x + v.y * v.y + v.z * v.z + v.w * v.w;
        }
    }
    if (lane < 20) xs[wy][300 + lane] = 0.f;
    #pragma unroll
    for (int o = 16; o > 0; o >>= 1) s += __shfl_xor_sync(0xffffffffu, s, o);
    s = __shfl_sync(0xffffffffu, s, 0);
    float rn = (row == 0) ? 0.f : 1.f / (sqrtf(s) + 1e-9f);
    __syncwarp();

    uint32_t* dst = g_h + (size_t)row * ROWW;
    #pragma unroll
    for (int k = 0; k < 5; k++) {
        int W = lane + 32 * k;
        int pair  = W >> 4;
        int rem   = W & 15;
        int j     = rem >> 2;
        int cl    = (rem >> 1) & 1;
        int wslot = rem & 1;
        int c  = pair * 2 + cl;
        int d0 = c * 16 + wslot * 8 + 2 * j;
        __half2 h2 = __floats2half2_rn(xs[wy][d0] * rn, xs[wy][d0 + 1] * rn);
        dst[W] = *(uint32_t*)&h2;
    }
}

// mma.sync m16n8k16 row.col f32.f16.f16.f32
#define MMA(c, a0, a1, a2, a3, b0, b1)                                        \
    asm volatile("mma.sync.aligned.m16n8k16.row.col.f32.f16.f16.f32 "         \
        "{%0,%1,%2,%3}, {%4,%5,%6,%7}, {%8,%9}, {%0,%1,%2,%3};"               \
        : "+f"((c)[0]), "+f"((c)[1]), "+f"((c)[2]), "+f"((c)[3])              \
        : "r"(a0), "r"(a1), "r"(a2), "r"(a3), "r"(b0), "r"(b1))

// ---------------- main kernel: one 128-thread CTA per (batch, doc) ----------------
__global__ __launch_bounds__(NTHR, 4) void knrm_mma_kernel(
    const int*   __restrict__ posdoc,
    const int*   __restrict__ negdoc,
    const int*   __restrict__ query,
    const float* __restrict__ W,
    const float* __restrict__ bparam,
    float*       __restrict__ out)
{
    // B tiles: [c][lane] uint4 = {h0 uint2, h1 uint2} for (n=lane>>2, j=lane&3)
    __shared__ uint4 Bsm[NCH * 32];          // 10 KB
    __shared__ int   toks[T_LEN];            // 4 KB
    __shared__ float wacc[NWARP * 192];
    __shared__ float red[192];
    __shared__ int   qtok[Q_LEN];
    __shared__ float spart[11];

    const int tid  = threadIdx.x;
    const int w    = tid >> 5;
    const int lane = tid & 31;
    const int bi    = blockIdx.x >> 1;
    const int which = blockIdx.x & 1;
    const int* doc  = which ? negdoc : posdoc;

    if (tid < Q_LEN) qtok[tid] = query[bi * Q_LEN + tid];
    // stage all doc tokens (coalesced)
    #pragma unroll
    for (int i = 0; i < T_LEN / NTHR; i++)
        toks[tid + i * NTHR] = doc[bi * T_LEN + tid + i * NTHR];
    __syncthreads();

    // ---- build B tiles (query): packed both n-halves per lane slot ----
    for (int idx = tid; idx < NCH * 32; idx += NTHR) {
        int l = idx & 31;
        int c = idx >> 5;
        int n = l >> 2, j = l & 3;
        const uint32_t* s0 = g_h + (size_t)qtok[n] * ROWW +
                             (c >> 1) * 16 + j * 4 + (c & 1) * 2;
        const uint32_t* s1 = g_h + (size_t)qtok[8 + n] * ROWW +
                             (c >> 1) * 16 + j * 4 + (c & 1) * 2;
        Bsm[idx] = make_uint4(s0[0], s0[1], s1[0], s1[1]);
    }
    __syncthreads();

    const int j4 = lane & 3;

    float kacc[44];
    float ssum4[4];
    #pragma unroll
    for (int v = 0; v < 44; v++) kacc[v] = 0.f;
    #pragma unroll
    for (int v = 0; v < 4; v++) ssum4[v] = 0.f;

    const float cC[10] = {2.5767571e-18f, 2.2897348e-11f, 3.7266532e-06f,
                          1.1108997e-02f, 6.0653067e-01f, 6.0653067e-01f,
                          1.1108997e-02f, 3.7266532e-06f, 2.2897348e-11f,
                          2.5767571e-18f};

    const int wbase = w * (T_LEN / NWARP);
    int tokA = toks[wbase + (lane >> 2)];
    int tokB = toks[wbase + 8 + (lane >> 2)];

    for (int tt = 0; tt < TPW; tt++) {
        const uint4* pa = (const uint4*)(g_h + (size_t)tokA * ROWW) + j4;
        const uint4* pb = (const uint4*)(g_h + (size_t)tokB * ROWW) + j4;

        float c0[4] = {0.f, 0.f, 0.f, 0.f};   // q cols 0-7
        float c1[4] = {0.f, 0.f, 0.f, 0.f};   // q cols 8-15

        uint4 va = pa[0];
        uint4 vb = pb[0];

        #pragma unroll
        for (int p = 0; p < 10; p++) {
            uint4 na = va, nb = vb;
            if (p < 9) {
                na = pa[(p + 1) * 4];
                nb = pb[(p + 1) * 4];
            }
            // chunk 2p
            {
                uint4 B = Bsm[(2 * p) * 32 + lane];
                MMA(c0, va.x, vb.x, va.y, vb.y, B.x, B.y);
                MMA(c1, va.x, vb.x, va.y, vb.y, B.z, B.w);
            }
            // chunk 2p+1
            {
                uint4 B = Bsm[(2 * p + 1) * 32 + lane];
                MMA(c0, va.z, vb.z, va.w, vb.w, B.x, B.y);
                MMA(c1, va.z, vb.z, va.w, vb.w, B.z, B.w);
            }
            va = na; vb = nb;
        }

        // prefetch next tile's tokens (from smem) before the epilogue
        if (tt < TPW - 1) {
            tokA = toks[wbase + (tt + 1) * 16 + (lane >> 2)];
            tokB = toks[wbase + (tt + 1) * 16 + 8 + (lane >> 2)];
        }

        // ---- fused RBF epilogue on C-fragment registers ----
        #pragma unroll
        for (int nh = 0; nh < 2; nh++) {
            #pragma unroll
            for (int j = 0; j < 4; j++) {
                float s = nh ? c1[j] : c0[j];
                int c2 = nh * 2 + (j & 1);
                ssum4[c2] += s;
                float A = -50.f * s * s;
                float e = __expf(A);
                float u = __expf(10.f * s);
                float r;
                asm("rcp.approx.f32 %0, %1;" : "=f"(r) : "f"(u));
                float u2 = u * u, u3 = u2 * u, u5 = u3 * u2, u7 = u5 * u2;
                float r2 = r * r, r3 = r2 * r, r5 = r3 * r2, r7 = r5 * r2;
                kacc[0 * 4 + c2] += cC[0] * __expf(fmaf(-90.f, s, A));
                kacc[1 * 4 + c2] += cC[1] * (e * r7);
                kacc[2 * 4 + c2] += cC[2] * (e * r5);
                kacc[3 * 4 + c2] += cC[3] * (e * r3);
                kacc[4 * 4 + c2] += cC[4] * (e * r);
                kacc[5 * 4 + c2] += cC[5] * (e * u);
                kacc[6 * 4 + c2] += cC[6] * (e * u3);
                kacc[7 * 4 + c2] += cC[7] * (e * u5);
                kacc[8 * 4 + c2] += cC[8] * (e * u7);
                kacc[9 * 4 + c2] += cC[9] * __expf(fmaf(90.f, s, A));
                float d1 = s - 1.f;
                kacc[40 + c2] += __expf(-500000.f * d1 * d1);
            }
        }
    }

    // ---- warp reduce over row-group lanes (bits 2..4 of lane) ----
    #pragma unroll
    for (int v = 0; v < 44; v++) {
        float x = kacc[v];
        x += __shfl_xor_sync(0xffffffffu, x, 4);
        x += __shfl_xor_sync(0xffffffffu, x, 8);
        x += __shfl_xor_sync(0xffffffffu, x, 16);
        kacc[v] = x;
    }
    #pragma unroll
    for (int c2 = 0; c2 < 4; c2++) {
        float x = ssum4[c2];
        x += __shfl_xor_sync(0xffffffffu, x, 4);
        x += __shfl_xor_sync(0xffffffffu, x, 8);
        x += __shfl_xor_sync(0xffffffffu, x, 16);
        ssum4[c2] = x;
    }

    if (lane < 4) {
        #pragma unroll
        for (int k = 0; k < 11; k++) {
            wacc[w * 192 + k * 16 + 2 * lane    ] = kacc[k * 4 + 0];
            wacc[w * 192 + k * 16 + 2 * lane + 1] = kacc[k * 4 + 1];
            wacc[w * 192 + k * 16 + 2 * lane + 8] = kacc[k * 4 + 2];
            wacc[w * 192 + k * 16 + 2 * lane + 9] = kacc[k * 4 + 3];
        }
        wacc[w * 192 + 176 + 2 * lane    ] = ssum4[0];
        wacc[w * 192 + 176 + 2 * lane + 1] = ssum4[1];
        wacc[w * 192 + 176 + 2 * lane + 8] = ssum4[2];
        wacc[w * 192 + 176 + 2 * lane + 9] = ssum4[3];
    }
    __syncthreads();

    for (int idx = tid; idx < 192; idx += NTHR) {
        float s = 0.f;
        #pragma unroll
        for (int ww = 0; ww < NWARP; ww++) s += wacc[ww * 192 + idx];
        red[idx] = s;
    }
    __syncthreads();

    if (tid < 11) {
        float qk = 0.f;
        #pragma unroll
        for (int q = 0; q < Q_LEN; q++)
            if (red[176 + q] != 0.0f) qk += logf(red[tid * 16 + q] + 1e-6f);
        spart[tid] = qk * W[tid];
    }
    __syncthreads();
    if (tid == 0) {
        float s = bparam[0];
        #pragma unroll
        for (int k = 0; k < 11; k++) s += spart[k];
        out[bi * 2 + which] = s;
    }
}

extern "C" void kernel_launch(void* const* d_in, const int* in_sizes, int n_in,
                              void* d_out, int out_size) {
    const int*   posdoc = (const int*)d_in[0];
    const int*   negdoc = (const int*)d_in[1];
    const int*   query  = (const int*)d_in[2];
    // d_in[3] = query_idf (unused)
    const float* emb    = (const float*)d_in[4];
    // d_in[5] = mus, d_in[6] = sigmas (compile-time folded)
    const float* W      = (const float*)d_in[7];
    const float* bparam = (const float*)d_in[8];
    float* out = (float*)d_out;

    prep_kernel<<<(V_SIZE + 7) / 8, dim3(32, 8)>>>(emb);
    knrm_mma_kernel<<<512, NTHR>>>(posdoc, negdoc, query, W, bparam, out);
}

// round 14
// speedup vs baseline: 2.8371x; 1.0385x over previous
#include <cuda_runtime.h>
#include <cuda_fp16.h>
#include <stdint.h>

#define V_SIZE 50000
#define D_DIM  300
#define ROWW   160      // uint32 words per row (320 fp16 = 640B)
#define NCH    20       // k16 chunks over 320 padded dims
#define Q_LEN  16
#define T_LEN  1024
#define NTHR   64
#define NWARP  2
#define TPW    16       // tiles per warp (16 tokens each)

// fp16 normalized embeddings, fragment-ordered for mma.m16n8k16 (see R12/R13)
__device__ uint32_t g_h[(size_t)V_SIZE * ROWW];
// per-(doc,half) partials: [11 k][16 q] + ssum[16]
__device__ float g_part[1024][192];

// ---------------- prep: normalize + fp16 + fragment order ----------------
__global__ void prep_kernel(const float* __restrict__ emb) {
    __shared__ float xs[8][320];
    int row = blockIdx.x * 8 + threadIdx.y;
    if (row >= V_SIZE) return;
    int lane = threadIdx.x;
    int wy = threadIdx.y;
    const float4* r4 = (const float4*)(emb + (size_t)row * D_DIM);  // 75 float4
    float s = 0.f;
    #pragma unroll
    for (int i = 0; i < 3; i++) {
        int idx = lane + 32 * i;
        if (idx < 75) {
            float4 v = r4[idx];
            xs[wy][idx * 4 + 0] = v.x;
            xs[wy][idx * 4 + 1] = v.y;
            xs[wy][idx * 4 + 2] = v.z;
            xs[wy][idx * 4 + 3] = v.w;
            s += v.x * v.x + v.y * v.y + v.z * v.z + v.w * v.w;
        }
    }
    if (lane < 20) xs[wy][300 + lane] = 0.f;
    #pragma unroll
    for (int o = 16; o > 0; o >>= 1) s += __shfl_xor_sync(0xffffffffu, s, o);
    s = __shfl_sync(0xffffffffu, s, 0);
    float rn = (row == 0) ? 0.f : 1.f / (sqrtf(s) + 1e-9f);
    __syncwarp();

    uint32_t* dst = g_h + (size_t)row * ROWW;
    #pragma unroll
    for (int k = 0; k < 5; k++) {
        int W = lane + 32 * k;
        int pair  = W >> 4;
        int rem   = W & 15;
        int j     = rem >> 2;
        int cl    = (rem >> 1) & 1;
        int wslot = rem & 1;
        int c  = pair * 2 + cl;
        int d0 = c * 16 + wslot * 8 + 2 * j;
        __half2 h2 = __floats2half2_rn(xs[wy][d0] * rn, xs[wy][d0 + 1] * rn);
        dst[W] = *(uint32_t*)&h2;
    }
}

// mma.sync m16n8k16 row.col f32.f16.f16.f32
#define MMA(c, a0, a1, a2, a3, b0, b1)                                        \
    asm volatile("mma.sync.aligned.m16n8k16.row.col.f32.f16.f16.f32 "         \
        "{%0,%1,%2,%3}, {%4,%5,%6,%7}, {%8,%9}, {%0,%1,%2,%3};"               \
        : "+f"((c)[0]), "+f"((c)[1]), "+f"((c)[2]), "+f"((c)[3])              \
        : "r"(a0), "r"(a1), "r"(a2), "r"(a3), "r"(b0), "r"(b1))

// ---------------- main kernel: 64-thread CTA per (batch, doc, half) ----------------
__global__ __launch_bounds__(NTHR, 8) void knrm_mma_kernel(
    const int*   __restrict__ posdoc,
    const int*   __restrict__ negdoc,
    const int*   __restrict__ query)
{
    __shared__ uint4 Bsm[NCH * 32];          // 10 KB: [c][lane] both n-halves
    __shared__ int   toks[T_LEN / 2];        // 2 KB
    __shared__ float wacc[NWARP * 192];
    __shared__ int   qtok[Q_LEN];

    const int tid  = threadIdx.x;
    const int w    = tid >> 5;
    const int lane = tid & 31;
    const int bx    = blockIdx.x;
    const int bi    = bx >> 2;
    const int which = (bx >> 1) & 1;
    const int half  = bx & 1;
    const int* doc  = which ? negdoc : posdoc;
    const int dbase = bi * T_LEN + half * (T_LEN / 2);

    if (tid < Q_LEN) qtok[tid] = query[bi * Q_LEN + tid];
    // stage this half's doc tokens (coalesced)
    #pragma unroll
    for (int i = 0; i < (T_LEN / 2) / NTHR; i++)
        toks[tid + i * NTHR] = doc[dbase + tid + i * NTHR];
    __syncthreads();

    // ---- build B tiles (query): packed both n-halves per lane slot ----
    for (int idx = tid; idx < NCH * 32; idx += NTHR) {
        int l = idx & 31;
        int c = idx >> 5;
        int n = l >> 2, j = l & 3;
        const uint32_t* s0 = g_h + (size_t)qtok[n] * ROWW +
                             (c >> 1) * 16 + j * 4 + (c & 1) * 2;
        const uint32_t* s1 = g_h + (size_t)qtok[8 + n] * ROWW +
                             (c >> 1) * 16 + j * 4 + (c & 1) * 2;
        Bsm[idx] = make_uint4(s0[0], s0[1], s1[0], s1[1]);
    }
    __syncthreads();

    const int j4 = lane & 3;

    float kacc[44];
    float ssum4[4];
    #pragma unroll
    for (int v = 0; v < 44; v++) kacc[v] = 0.f;
    #pragma unroll
    for (int v = 0; v < 4; v++) ssum4[v] = 0.f;

    const int wbase = w * (T_LEN / 2 / NWARP);
    int tokA = toks[wbase + (lane >> 2)];
    int tokB = toks[wbase + 8 + (lane >> 2)];

    for (int tt = 0; tt < TPW; tt++) {
        const uint4* pa = (const uint4*)(g_h + (size_t)tokA * ROWW) + j4;
        const uint4* pb = (const uint4*)(g_h + (size_t)tokB * ROWW) + j4;

        float c0[4] = {0.f, 0.f, 0.f, 0.f};   // q cols 0-7
        float c1[4] = {0.f, 0.f, 0.f, 0.f};   // q cols 8-15

        uint4 va = pa[0];
        uint4 vb = pb[0];

        #pragma unroll
        for (int p = 0; p < 10; p++) {
            uint4 na = va, nb = vb;
            if (p < 9) {
                na = pa[(p + 1) * 4];
                nb = pb[(p + 1) * 4];
            }
            {
                uint4 B = Bsm[(2 * p) * 32 + lane];
                MMA(c0, va.x, vb.x, va.y, vb.y, B.x, B.y);
                MMA(c1, va.x, vb.x, va.y, vb.y, B.z, B.w);
            }
            {
                uint4 B = Bsm[(2 * p + 1) * 32 + lane];
                MMA(c0, va.z, vb.z, va.w, vb.w, B.x, B.y);
                MMA(c1, va.z, vb.z, va.w, vb.w, B.z, B.w);
            }
            va = na; vb = nb;
        }

        if (tt < TPW - 1) {
            tokA = toks[wbase + (tt + 1) * 16 + (lane >> 2)];
            tokB = toks[wbase + (tt + 1) * 16 + 8 + (lane >> 2)];
        }

        // ---- fused RBF epilogue: ladder form (3 exps + 1 rcp per sim) ----
        #pragma unroll
        for (int nh = 0; nh < 2; nh++) {
            #pragma unroll
            for (int j = 0; j < 4; j++) {
                float s = nh ? c1[j] : c0[j];
                int c2 = nh * 2 + (j & 1);
                ssum4[c2] += s;
                float s2 = s * s;
                float e  = __expf(-50.f * s2);
                float u  = __expf(10.f * s);
                float r;
                asm("rcp.approx.f32 %0, %1;" : "=f"(r) : "f"(u));
                float u2 = u * u, r2 = r * r;
                float t = e * r;                               // exp(-50s^2-10s)
                kacc[16 + c2] += 6.0653067e-01f * t;           // mu=-0.1
                t *= r2; kacc[12 + c2] += 1.1108997e-02f * t;  // mu=-0.3
                t *= r2; kacc[ 8 + c2] += 3.7266532e-06f * t;  // mu=-0.5
                t *= r2; kacc[ 4 + c2] += 2.2897348e-11f * t;  // mu=-0.7
                t *= r2; kacc[ 0 + c2] += 2.5767571e-18f * t;  // mu=-0.9
                t = e * u;                                     // exp(-50s^2+10s)
                kacc[20 + c2] += 6.0653067e-01f * t;           // mu=+0.1
                t *= u2; kacc[24 + c2] += 1.1108997e-02f * t;  // mu=+0.3
                t *= u2; kacc[28 + c2] += 3.7266532e-06f * t;  // mu=+0.5
                t *= u2; kacc[32 + c2] += 2.2897348e-11f * t;  // mu=+0.7
                t *= u2; kacc[36 + c2] += 2.5767571e-18f * t;  // mu=+0.9
                float d1 = s - 1.f;
                kacc[40 + c2] += __expf(-500000.f * d1 * d1);  // mu=1, sigma=1e-3
            }
        }
    }

    // ---- warp reduce over row-group lanes (bits 2..4 of lane) ----
    #pragma unroll
    for (int v = 0; v < 44; v++) {
        float x = kacc[v];
        x += __shfl_xor_sync(0xffffffffu, x, 4);
        x += __shfl_xor_sync(0xffffffffu, x, 8);
        x += __shfl_xor_sync(0xffffffffu, x, 16);
        kacc[v] = x;
    }
    #pragma unroll
    for (int c2 = 0; c2 < 4; c2++) {
        float x = ssum4[c2];
        x += __shfl_xor_sync(0xffffffffu, x, 4);
        x += __shfl_xor_sync(0xffffffffu, x, 8);
        x += __shfl_xor_sync(0xffffffffu, x, 16);
        ssum4[c2] = x;
    }

    if (lane < 4) {
        #pragma unroll
        for (int k = 0; k < 11; k++) {
            wacc[w * 192 + k * 16 + 2 * lane    ] = kacc[k * 4 + 0];
            wacc[w * 192 + k * 16 + 2 * lane + 1] = kacc[k * 4 + 1];
            wacc[w * 192 + k * 16 + 2 * lane + 8] = kacc[k * 4 + 2];
            wacc[w * 192 + k * 16 + 2 * lane + 9] = kacc[k * 4 + 3];
        }
        wacc[w * 192 + 176 + 2 * lane    ] = ssum4[0];
        wacc[w * 192 + 176 + 2 * lane + 1] = ssum4[1];
        wacc[w * 192 + 176 + 2 * lane + 8] = ssum4[2];
        wacc[w * 192 + 176 + 2 * lane + 9] = ssum4[3];
    }
    __syncthreads();

    float* dst = g_part[bx];
    #pragma unroll
    for (int i = tid; i < 192; i += NTHR)
        dst[i] = wacc[i] + wacc[192 + i];
}

// ---------------- finalize: one warp per (batch, doc) ----------------
__global__ __launch_bounds__(32) void finalize_kernel(
    const float* __restrict__ W,
    const float* __restrict__ bparam,
    float*       __restrict__ out)
{
    const int d = blockIdx.x;      // 0..511 = bi*2 + which
    const int lane = threadIdx.x;
    __shared__ float v[192];
    const float* p0 = g_part[2 * d];
    const float* p1 = g_part[2 * d + 1];
    #pragma unroll
    for (int i = lane; i < 192; i += 32) v[i] = p0[i] + p1[i];
    __syncwarp();
    float acc = 0.f;
    #pragma unroll
    for (int m = 0; m < 6; m++) {
        int idx = lane + 32 * m;
        if (idx < 176) {
            int k = idx >> 4, q = idx & 15;
            if (v[176 + q] != 0.0f)
                acc += W[k] * logf(v[idx] + 1e-6f);
        }
    }
    #pragma unroll
    for (int o = 16; o > 0; o >>= 1) acc += __shfl_xor_sync(0xffffffffu, acc, o);
    if (lane == 0) out[d] = acc + bparam[0];
}

extern "C" void kernel_launch(void* const* d_in, const int* in_sizes, int n_in,
                              void* d_out, int out_size) {
    const int*   posdoc = (const int*)d_in[0];
    const int*   negdoc = (const int*)d_in[1];
    const int*   query  = (const int*)d_in[2];
    // d_in[3] = query_idf (unused)
    const float* emb    = (const float*)d_in[4];
    // d_in[5] = mus, d_in[6] = sigmas (compile-time folded)
    const float* W      = (const float*)d_in[7];
    const float* bparam = (const float*)d_in[8];
    float* out = (float*)d_out;

    prep_kernel<<<(V_SIZE + 7) / 8, dim3(32, 8)>>>(emb);
    knrm_mma_kernel<<<1024, NTHR>>>(posdoc, negdoc, query);
    finalize_kernel<<<512, 32>>>(W, bparam, out);
}